// round 14
// baseline (speedup 1.0000x reference)
#include <cuda_runtime.h>
#include <cstdint>

#define DFEAT 48
#define NCG   12                       // float4 column-groups per row (48/4)
#define CHUNK 256                      // edges per block in k_main
#define NWALK 32                       // row-walkers per column-group
#define WALKR (CHUNK / NWALK)          // 8 rows per walker
#define MAIN_THREADS (NCG * NWALK)     // 384

#define QUARTER_ROWS  (CHUNK / 4)                  // 64 rows per TMA quarter
#define QUARTER_BYTES (QUARTER_ROWS * DFEAT * 4)   // 12288
#define FT_TILE_BYTES (CHUNK * DFEAT * 4)          // 49152 (48KB)
#define SMEM_W_OFF    FT_TILE_BYTES                // w_s: CHUNK floats
#define SMEM_S_OFF    (FT_TILE_BYTES + CHUNK * 4)  // s_s: CHUNK ints
#define SMEM_MBAR_OFF (FT_TILE_BYTES + CHUNK * 8)  // mbar[4]
#define SMEM_TOTAL    (SMEM_MBAR_OFF + 64)

// Per-node softmax denominators (N = 50000 here; padded)
__device__ float g_denom[65536];

// Edge-parallel denom accumulation (8 consecutive edges/thread, float4/int4
// loads, run-aggregated atomics on sorted sids) + fused grid-stride zeroing
// of the output buffer. Triggers PDL immediately so k_main's independent
// prologue (TMA issue + exp staging) overlaps this kernel.
__global__ void k_exp(const float* __restrict__ a,
                      const int* __restrict__ seg, int E,
                      float4* __restrict__ out4, int out_n4) {
#if __CUDA_ARCH__ >= 900
    cudaTriggerProgrammaticLaunchCompletion();
#endif
    int t = blockIdx.x * blockDim.x + threadIdx.x;

    // Fused: zero the output (harness poisons it to 0xAA)
    int nthreads = gridDim.x * blockDim.x;
    for (int i = t; i < out_n4; i += nthreads)
        out4[i] = make_float4(0.f, 0.f, 0.f, 0.f);

    int e0 = t * 8;
    if (e0 >= E) return;

    if (e0 + 8 <= E) {
        float acc = 0.0f;
        int cur = -1;
        #pragma unroll
        for (int h = 0; h < 2; h++) {
            float4 av = *(const float4*)(a + e0 + h * 4);
            int4   sv = *(const int4*)(seg + e0 + h * 4);
            float ex[4] = {__expf(av.x), __expf(av.y), __expf(av.z), __expf(av.w)};
            int   sd[4] = {sv.x, sv.y, sv.z, sv.w};
            #pragma unroll
            for (int k = 0; k < 4; k++) {
                if (sd[k] != cur) {
                    if (cur >= 0) atomicAdd(&g_denom[cur], acc);
                    acc = 0.0f; cur = sd[k];
                }
                acc += ex[k];
            }
        }
        atomicAdd(&g_denom[cur], acc);
    } else {
        for (int e = e0; e < E; e++)
            atomicAdd(&g_denom[seg[e]], __expf(a[e]));
    }
}

__device__ __forceinline__ uint32_t smem_u32(const void* p) {
    return (uint32_t)__cvta_generic_to_shared(p);
}
__device__ __forceinline__ void mbar_init(uint32_t mbar, uint32_t count) {
    asm volatile("mbarrier.init.shared.b64 [%0], %1;" :: "r"(mbar), "r"(count) : "memory");
}
__device__ __forceinline__ void mbar_expect_tx(uint32_t mbar, uint32_t bytes) {
    asm volatile("mbarrier.arrive.expect_tx.shared.b64 _, [%0], %1;"
                 :: "r"(mbar), "r"(bytes) : "memory");
}
__device__ __forceinline__ void bulk_g2s(uint32_t dst_smem, const void* src_gmem,
                                         uint32_t bytes, uint32_t mbar) {
    asm volatile(
        "cp.async.bulk.shared::cta.global.mbarrier::complete_tx::bytes "
        "[%0], [%1], %2, [%3];"
        :: "r"(dst_smem), "l"(src_gmem), "r"(bytes), "r"(mbar) : "memory");
}
__device__ __forceinline__ void mbar_wait(uint32_t mbar, uint32_t parity) {
    asm volatile(
        "{\n\t"
        ".reg .pred P;\n\t"
        "W%=:\n\t"
        "mbarrier.try_wait.parity.shared::cta.b64 P, [%0], %1;\n\t"
        "@!P bra W%=;\n\t"
        "}"
        :: "r"(mbar), "r"(parity) : "memory");
}

// Vectorized global reduction: one instruction instead of 4 scalar REDs.
__device__ __forceinline__ void red_add_v4(float* p, float4 v) {
    asm volatile("red.global.add.v4.f32 [%0], {%1, %2, %3, %4};"
                 :: "l"(p), "f"(v.x), "f"(v.y), "f"(v.z), "f"(v.w) : "memory");
}

// Main pass: block = 256 contiguous edges, 48KB tile split into FOUR 12KB
// TMA copies with separate mbarriers — each warp waits only on the quarter
// holding its rows, so compute starts after ~1/4 of the tile lands and each
// block keeps 4 outstanding bulk copies. 4 blocks/SM interleave phases so
// DRAM never idles. Launched via PDL: TMA issue and exp/sid staging run
// before the grid dependency sync; only the denom division waits on k_exp.
// Compute: 12 float4-column-groups x 32 row-walkers from smem; red.v4 flush
// only at segment boundaries (seg is sorted).
__global__ void __launch_bounds__(MAIN_THREADS, 4)
k_main(const float* __restrict__ a,
       const float* __restrict__ ft,
       const int* __restrict__ seg,
       float* __restrict__ out, int E) {
    extern __shared__ __align__(128) char smem[];
    float4* s_ft = (float4*)smem;
    float*  w_s  = (float*)(smem + SMEM_W_OFF);
    int*    s_s  = (int*)(smem + SMEM_S_OFF);
    uint32_t mb0 = smem_u32(smem + SMEM_MBAR_OFF);

    int base = blockIdx.x * CHUNK;
    int tid  = threadIdx.x;
    bool full = (base + CHUNK <= E);

    if (tid == 0) {
        #pragma unroll
        for (int q = 0; q < 4; q++) mbar_init(mb0 + q * 8, 1);
    }
    __syncthreads();

    if (full && tid == 0) {
        #pragma unroll
        for (int q = 0; q < 4; q++) {
            uint32_t mb = mb0 + q * 8;
            mbar_expect_tx(mb, QUARTER_BYTES);
            bulk_g2s(smem_u32(s_ft) + q * QUARTER_BYTES,
                     ft + (size_t)(base + q * QUARTER_ROWS) * DFEAT,
                     QUARTER_BYTES, mb);
        }
    }

    // Stage exp(a) and sid (independent of k_exp's denominators)
    float ex = 0.0f;
    int   sid_t = -1;
    if (tid < CHUNK) {
        int e = base + tid;
        if (e < E) {
            sid_t = seg[e];
            ex = __expf(a[e]);
        }
        s_s[tid] = sid_t;
    }

    if (!full) {
        // Tail chunk: guarded per-thread loads into smem
        const float4* ft4 = (const float4*)ft;
        for (int i = tid; i < CHUNK * NCG; i += MAIN_THREADS) {
            int row = base + i / NCG;
            s_ft[i] = (row < E) ? ft4[(size_t)row * NCG + (i % NCG)]
                                : make_float4(0.f, 0.f, 0.f, 0.f);
        }
    }

#if __CUDA_ARCH__ >= 900
    cudaGridDependencySynchronize();   // k_exp (denom + out zero) complete
#endif

    if (tid < CHUNK)
        w_s[tid] = (sid_t >= 0) ? __fdividef(ex, g_denom[sid_t]) : 0.0f;

    __syncthreads();

    int cg = tid % NCG;            // float4 column group (0..11)
    int y  = tid / NCG;            // walker id (0..31)
    int j0 = y * WALKR;

    // Each warp waits only on the quarter containing its rows.
    if (full) mbar_wait(mb0 + (j0 / QUARTER_ROWS) * 8, 0);

    int    cur = s_s[j0];
    float4 acc = make_float4(0.f, 0.f, 0.f, 0.f);

    #pragma unroll
    for (int k = 0; k < WALKR; k++) {
        int j = j0 + k;
        int    sid = s_s[j];
        float  w   = w_s[j];
        float4 v   = s_ft[j * NCG + cg];
        if (sid != cur) {
            if (cur >= 0) red_add_v4(out + (size_t)cur * DFEAT + cg * 4, acc);
            acc = make_float4(0.f, 0.f, 0.f, 0.f);
            cur = sid;
        }
        acc.x += w * v.x;
        acc.y += w * v.y;
        acc.z += w * v.z;
        acc.w += w * v.w;
    }
    if (cur >= 0) red_add_v4(out + (size_t)cur * DFEAT + cg * 4, acc);
}

extern "C" void kernel_launch(void* const* d_in, const int* in_sizes, int n_in,
                              void* d_out, int out_size) {
    const float* a   = (const float*)d_in[0];
    const float* ft  = (const float*)d_in[1];
    const int*   seg = (const int*)d_in[2];
    float* out = (float*)d_out;

    int E = in_sizes[0];

    // Zero denominators directly on the device symbol (no kernel launch).
    void* denom_ptr = nullptr;
    cudaGetSymbolAddress(&denom_ptr, g_denom);
    cudaMemsetAsync(denom_ptr, 0, sizeof(g_denom));

    // k_exp also zeroes the output buffer (fused).
    int e8 = (E + 7) / 8;
    k_exp<<<(e8 + 255) / 256, 256>>>(a, seg, E, (float4*)out, out_size / 4);

    cudaFuncSetAttribute(k_main, cudaFuncAttributeMaxDynamicSharedMemorySize,
                         SMEM_TOTAL);
    int mb = (E + CHUNK - 1) / CHUNK;

    // PDL launch: k_main's prologue overlaps k_exp.
    cudaLaunchConfig_t cfg = {};
    cfg.gridDim = dim3(mb);
    cfg.blockDim = dim3(MAIN_THREADS);
    cfg.dynamicSmemBytes = SMEM_TOTAL;
    cudaLaunchAttribute attrs[1];
    attrs[0].id = cudaLaunchAttributeProgrammaticStreamSerialization;
    attrs[0].val.programmaticStreamSerializationAllowed = 1;
    cfg.attrs = attrs;
    cfg.numAttrs = 1;
    cudaLaunchKernelEx(&cfg, k_main, a, ft, seg, out, E);
}

// round 15
// speedup vs baseline: 1.1337x; 1.1337x over previous
#include <cuda_runtime.h>
#include <cstdint>

#define DFEAT 48
#define NCG   12                       // float4 column-groups per row (48/4)
#define CHUNK 256                      // edges per block in k_main
#define NWALK 32                       // row-walkers per column-group
#define WALKR (CHUNK / NWALK)          // 8 rows per walker
#define MAIN_THREADS (NCG * NWALK)     // 384

#define HALF_ROWS     (CHUNK / 2)                  // 128 rows per TMA half
#define HALF_BYTES    (HALF_ROWS * DFEAT * 4)      // 24576
#define FT_TILE_BYTES (CHUNK * DFEAT * 4)          // 49152 (48KB)
#define SMEM_W_OFF    FT_TILE_BYTES                // w_s: CHUNK floats
#define SMEM_S_OFF    (FT_TILE_BYTES + CHUNK * 4)  // s_s: CHUNK ints
#define SMEM_MBAR_OFF (FT_TILE_BYTES + CHUNK * 8)  // mbar[2]
#define SMEM_TOTAL    (SMEM_MBAR_OFF + 32)

// Per-node softmax denominators (N = 50000 here; padded)
__device__ float g_denom[65536];

// Edge-parallel denom accumulation (8 consecutive edges/thread, float4/int4
// loads, run-aggregated atomics on sorted sids) + fused grid-stride zeroing
// of the output buffer. Triggers PDL immediately so k_main's independent
// prologue (TMA issue + exp staging) overlaps this kernel.
__global__ void k_exp(const float* __restrict__ a,
                      const int* __restrict__ seg, int E,
                      float4* __restrict__ out4, int out_n4) {
#if __CUDA_ARCH__ >= 900
    cudaTriggerProgrammaticLaunchCompletion();
#endif
    int t = blockIdx.x * blockDim.x + threadIdx.x;

    // Fused: zero the output (harness poisons it to 0xAA)
    int nthreads = gridDim.x * blockDim.x;
    for (int i = t; i < out_n4; i += nthreads)
        out4[i] = make_float4(0.f, 0.f, 0.f, 0.f);

    int e0 = t * 8;
    if (e0 >= E) return;

    if (e0 + 8 <= E) {
        float acc = 0.0f;
        int cur = -1;
        #pragma unroll
        for (int h = 0; h < 2; h++) {
            float4 av = *(const float4*)(a + e0 + h * 4);
            int4   sv = *(const int4*)(seg + e0 + h * 4);
            float ex[4] = {__expf(av.x), __expf(av.y), __expf(av.z), __expf(av.w)};
            int   sd[4] = {sv.x, sv.y, sv.z, sv.w};
            #pragma unroll
            for (int k = 0; k < 4; k++) {
                if (sd[k] != cur) {
                    if (cur >= 0) atomicAdd(&g_denom[cur], acc);
                    acc = 0.0f; cur = sd[k];
                }
                acc += ex[k];
            }
        }
        atomicAdd(&g_denom[cur], acc);
    } else {
        for (int e = e0; e < E; e++)
            atomicAdd(&g_denom[seg[e]], __expf(a[e]));
    }
}

__device__ __forceinline__ uint32_t smem_u32(const void* p) {
    return (uint32_t)__cvta_generic_to_shared(p);
}
__device__ __forceinline__ void mbar_init(uint32_t mbar, uint32_t count) {
    asm volatile("mbarrier.init.shared.b64 [%0], %1;" :: "r"(mbar), "r"(count) : "memory");
}
__device__ __forceinline__ void mbar_expect_tx(uint32_t mbar, uint32_t bytes) {
    asm volatile("mbarrier.arrive.expect_tx.shared.b64 _, [%0], %1;"
                 :: "r"(mbar), "r"(bytes) : "memory");
}
// Bulk copy with L2 evict_first hint: ft is streamed exactly once, so its
// sectors should be first eviction candidates, keeping out/a/seg/denom
// resident in L2 (out lines are hit by ~8M red.v4 ops).
__device__ __forceinline__ void bulk_g2s_stream(uint32_t dst_smem, const void* src_gmem,
                                                uint32_t bytes, uint32_t mbar) {
    uint64_t policy;
    asm volatile("createpolicy.fractional.L2::evict_first.b64 %0, 1.0;" : "=l"(policy));
    asm volatile(
        "cp.async.bulk.shared::cta.global.mbarrier::complete_tx::bytes.L2::cache_hint "
        "[%0], [%1], %2, [%3], %4;"
        :: "r"(dst_smem), "l"(src_gmem), "r"(bytes), "r"(mbar), "l"(policy) : "memory");
}
__device__ __forceinline__ void mbar_wait(uint32_t mbar, uint32_t parity) {
    asm volatile(
        "{\n\t"
        ".reg .pred P;\n\t"
        "W%=:\n\t"
        "mbarrier.try_wait.parity.shared::cta.b64 P, [%0], %1;\n\t"
        "@!P bra W%=;\n\t"
        "}"
        :: "r"(mbar), "r"(parity) : "memory");
}

// Vectorized global reduction: one instruction instead of 4 scalar REDs.
__device__ __forceinline__ void red_add_v4(float* p, float4 v) {
    asm volatile("red.global.add.v4.f32 [%0], {%1, %2, %3, %4};"
                 :: "l"(p), "f"(v.x), "f"(v.y), "f"(v.z), "f"(v.w) : "memory");
}

// Main pass: block = 256 contiguous edges. Tile split into two 24KB TMA
// copies (evict_first L2 hint) with separate mbarriers: warps consuming
// rows 0-127 wait only on the first half. 4 blocks/SM interleave TMA and
// compute phases so DRAM never idles. Launched via PDL: TMA issue and
// exp/sid staging run before the grid dependency sync; only the denom
// division waits on k_exp. Compute: 12 float4-column-groups x 32 row-
// walkers from smem; red.v4 flush only at segment boundaries (seg sorted).
__global__ void __launch_bounds__(MAIN_THREADS, 4)
k_main(const float* __restrict__ a,
       const float* __restrict__ ft,
       const int* __restrict__ seg,
       float* __restrict__ out, int E) {
    extern __shared__ __align__(128) char smem[];
    float4* s_ft = (float4*)smem;
    float*  w_s  = (float*)(smem + SMEM_W_OFF);
    int*    s_s  = (int*)(smem + SMEM_S_OFF);
    uint32_t mb0 = smem_u32(smem + SMEM_MBAR_OFF);

    int base = blockIdx.x * CHUNK;
    int tid  = threadIdx.x;
    bool full = (base + CHUNK <= E);

    if (tid == 0) { mbar_init(mb0, 1); mbar_init(mb0 + 8, 1); }
    __syncthreads();

    if (full && tid == 0) {
        mbar_expect_tx(mb0, HALF_BYTES);
        bulk_g2s_stream(smem_u32(s_ft), ft + (size_t)base * DFEAT, HALF_BYTES, mb0);
        mbar_expect_tx(mb0 + 8, HALF_BYTES);
        bulk_g2s_stream(smem_u32(s_ft) + HALF_BYTES,
                        ft + (size_t)(base + HALF_ROWS) * DFEAT, HALF_BYTES, mb0 + 8);
    }

    // Stage exp(a) and sid (independent of k_exp's denominators)
    float ex = 0.0f;
    int   sid_t = -1;
    if (tid < CHUNK) {
        int e = base + tid;
        if (e < E) {
            sid_t = seg[e];
            ex = __expf(a[e]);
        }
        s_s[tid] = sid_t;
    }

    if (!full) {
        // Tail chunk: guarded per-thread loads into smem
        const float4* ft4 = (const float4*)ft;
        for (int i = tid; i < CHUNK * NCG; i += MAIN_THREADS) {
            int row = base + i / NCG;
            s_ft[i] = (row < E) ? ft4[(size_t)row * NCG + (i % NCG)]
                                : make_float4(0.f, 0.f, 0.f, 0.f);
        }
    }

#if __CUDA_ARCH__ >= 900
    cudaGridDependencySynchronize();   // k_exp (denom + out zero) complete
#endif

    if (tid < CHUNK)
        w_s[tid] = (sid_t >= 0) ? __fdividef(ex, g_denom[sid_t]) : 0.0f;

    __syncthreads();

    int cg = tid % NCG;            // float4 column group (0..11)
    int y  = tid / NCG;            // walker id (0..31)
    int j0 = y * WALKR;

    // Warps consuming rows [0,128) wait on mb0; rows [128,256) on mb1.
    if (full) mbar_wait(j0 < HALF_ROWS ? mb0 : mb0 + 8, 0);

    int    cur = s_s[j0];
    float4 acc = make_float4(0.f, 0.f, 0.f, 0.f);

    #pragma unroll
    for (int k = 0; k < WALKR; k++) {
        int j = j0 + k;
        int    sid = s_s[j];
        float  w   = w_s[j];
        float4 v   = s_ft[j * NCG + cg];
        if (sid != cur) {
            if (cur >= 0) red_add_v4(out + (size_t)cur * DFEAT + cg * 4, acc);
            acc = make_float4(0.f, 0.f, 0.f, 0.f);
            cur = sid;
        }
        acc.x += w * v.x;
        acc.y += w * v.y;
        acc.z += w * v.z;
        acc.w += w * v.w;
    }
    if (cur >= 0) red_add_v4(out + (size_t)cur * DFEAT + cg * 4, acc);
}

extern "C" void kernel_launch(void* const* d_in, const int* in_sizes, int n_in,
                              void* d_out, int out_size) {
    const float* a   = (const float*)d_in[0];
    const float* ft  = (const float*)d_in[1];
    const int*   seg = (const int*)d_in[2];
    float* out = (float*)d_out;

    int E = in_sizes[0];

    // Zero denominators directly on the device symbol (no kernel launch).
    void* denom_ptr = nullptr;
    cudaGetSymbolAddress(&denom_ptr, g_denom);
    cudaMemsetAsync(denom_ptr, 0, sizeof(g_denom));

    // k_exp also zeroes the output buffer (fused).
    int e8 = (E + 7) / 8;
    k_exp<<<(e8 + 255) / 256, 256>>>(a, seg, E, (float4*)out, out_size / 4);

    cudaFuncSetAttribute(k_main, cudaFuncAttributeMaxDynamicSharedMemorySize,
                         SMEM_TOTAL);
    int mb = (E + CHUNK - 1) / CHUNK;

    // PDL launch: k_main's prologue overlaps k_exp.
    cudaLaunchConfig_t cfg = {};
    cfg.gridDim = dim3(mb);
    cfg.blockDim = dim3(MAIN_THREADS);
    cfg.dynamicSmemBytes = SMEM_TOTAL;
    cudaLaunchAttribute attrs[1];
    attrs[0].id = cudaLaunchAttributeProgrammaticStreamSerialization;
    attrs[0].val.programmaticStreamSerializationAllowed = 1;
    cfg.attrs = attrs;
    cfg.numAttrs = 1;
    cudaLaunchKernelEx(&cfg, k_main, a, ft, seg, out, E);
}